// round 13
// baseline (speedup 1.0000x reference)
#include <cuda_runtime.h>
#include <cuda_fp16.h>
#include <cstdint>

// ---------------------------------------------------------------------------
// mma.sync fp16 1-pass. R13: K mirrored to fp16 (written by qkv GEMM), staged
// per kt with q pre-multiplied (qk fp16 in smem, conflict-free reads) to kill
// the scattered K LDGs that dominated L1 (79.7% of peak in R12 profile).
// ---------------------------------------------------------------------------

__device__ __forceinline__ void mma16816h(float c[4], const uint32_t a[4],
                                          uint32_t b0, uint32_t b1) {
    asm volatile("mma.sync.aligned.m16n8k16.row.col.f32.f16.f16.f32 "
        "{%0,%1,%2,%3},{%4,%5,%6,%7},{%8,%9},{%0,%1,%2,%3};"
        : "+f"(c[0]), "+f"(c[1]), "+f"(c[2]), "+f"(c[3])
        : "r"(a[0]), "r"(a[1]), "r"(a[2]), "r"(a[3]), "r"(b0), "r"(b1));
}
__device__ __forceinline__ uint32_t pack2h(float v0, float v1) {
    __half2 hh = __floats2half2_rn(v0, v1);
    return *(uint32_t*)&hh;
}
__device__ __forceinline__ uint32_t hmul2u(uint32_t a, uint32_t b) {
    __half2 r = __hmul2(*(__half2*)&a, *(__half2*)&b);
    return *(uint32_t*)&r;
}

// ===== scratch =====
__device__ float g_QKV[512 * 768];          // [b*256+n][768] q|k|v
__device__ float g_att[2 * 8 * 256 * 256];  // [b][h][k][q]
__device__ float g_wt[512 * 256];
__device__ uint4 g_Wss[4096];   // [ks4][tp32][lane32] frag-linear fp16x2
__device__ uint4 g_Wed[2048];   // [ks16][tp4][lane32]
__device__ uint4 g_K16[512 * 32];  // fp16 mirror of K rows: [row][32 uint4]

__global__ void __launch_bounds__(256) zero_wt_kernel()
{
    int i = blockIdx.x * 256 + threadIdx.x;
    ((float4*)g_wt)[i] = make_float4(0.f, 0.f, 0.f, 0.f);
}

// ===== prep: W_ss frag image (fp16) =====
__global__ void __launch_bounds__(256) prep_wss_kernel(const float* __restrict__ W_ss)
{
    int idx = blockIdx.x * 256 + threadIdx.x;    // 4096 uint4
    int lane = idx & 31, tp = (idx >> 5) & 31, ks = idx >> 10;
    int gq = lane >> 2, tq = lane & 3;
    uint32_t r4[4];
#pragma unroll
    for (int r = 0; r < 4; r++) {
        int tile = 2 * tp + (r >> 1);
        int bsel = r & 1;
        int n = tile * 8 + gq;
        int e0 = ks * 16 + 2 * tq + 8 * bsel;
        r4[r] = pack2h(W_ss[e0 * 512 + n], W_ss[(e0 + 1) * 512 + n]);
    }
    g_Wss[idx] = make_uint4(r4[0], r4[1], r4[2], r4[3]);
}
// ===== prep: W_edges frag image (fp16) =====
__global__ void __launch_bounds__(256) prep_wed_kernel(const float* __restrict__ W_edges)
{
    int idx = blockIdx.x * 256 + threadIdx.x;    // 2048 uint4
    int lane = idx & 31, tp = (idx >> 5) & 3, ks = idx >> 7;
    int gq = lane >> 2, tq = lane & 3;
    uint32_t r4[4];
#pragma unroll
    for (int r = 0; r < 4; r++) {
        int tile = 2 * tp + (r >> 1);
        int bsel = r & 1;
        int e = tile * 8 + gq;
        int c0 = ks * 16 + 2 * tq + 8 * bsel;
        r4[r] = pack2h(W_edges[c0 * 64 + e], W_edges[(c0 + 1) * 64 + e]);
    }
    g_Wed[idx] = make_uint4(r4[0], r4[1], r4[2], r4[3]);
}

// ===== small GEMM with bias; mirrors K columns [256,512) to g_K16 fp16 =====
__global__ void __launch_bounds__(256) gemm_bias_kernel(
    const float* __restrict__ A, const float* __restrict__ B,
    const float* __restrict__ bias, float* __restrict__ C, int M, int K, int N)
{
    __shared__ float sA[2][16][33];
    __shared__ float sB[2][16][64];
    const int nb = N >> 6;
    const int m0 = (blockIdx.x / nb) << 5, n0 = (blockIdx.x % nb) << 6;
    const int tm = threadIdx.x >> 4, tn = threadIdx.x & 15;
    const int tt = threadIdx.x;
    const int am = tt >> 2, ak4 = (tt & 3) << 2;
    const int bk = tt >> 4, bn4 = (tt & 15) << 2;
    const int nk = K >> 4;

    float4 aR, bR;
    if (tt < 128) aR = *(const float4*)&A[(m0 + am) * K + ak4];
    bR = *(const float4*)&B[bk * N + n0 + bn4];
    if (tt < 128) {
        sA[0][ak4+0][am] = aR.x; sA[0][ak4+1][am] = aR.y;
        sA[0][ak4+2][am] = aR.z; sA[0][ak4+3][am] = aR.w;
    }
    *(float4*)&sB[0][bk][bn4] = bR;
    __syncthreads();

    float acc[2][4] = {};
    for (int kc = 0; kc < nk; kc++) {
        const int cur = kc & 1;
        if (kc + 1 < nk) {
            if (tt < 128) aR = *(const float4*)&A[(m0 + am) * K + (kc+1)*16 + ak4];
            bR = *(const float4*)&B[((kc+1)*16 + bk) * N + n0 + bn4];
        }
#pragma unroll
        for (int k2 = 0; k2 < 16; k2++) {
            float a0 = sA[cur][k2][tm*2+0], a1 = sA[cur][k2][tm*2+1];
            float4 b4 = *(float4*)&sB[cur][k2][tn*4];
            acc[0][0]+=a0*b4.x; acc[0][1]+=a0*b4.y; acc[0][2]+=a0*b4.z; acc[0][3]+=a0*b4.w;
            acc[1][0]+=a1*b4.x; acc[1][1]+=a1*b4.y; acc[1][2]+=a1*b4.z; acc[1][3]+=a1*b4.w;
        }
        if (kc + 1 < nk) {
            const int nxt = cur ^ 1;
            if (tt < 128) {
                sA[nxt][ak4+0][am] = aR.x; sA[nxt][ak4+1][am] = aR.y;
                sA[nxt][ak4+2][am] = aR.z; sA[nxt][ak4+3][am] = aR.w;
            }
            *(float4*)&sB[nxt][bk][bn4] = bR;
        }
        __syncthreads();
    }
    float4 bb = *(const float4*)&bias[n0 + tn * 4];
#pragma unroll
    for (int i = 0; i < 2; i++) {
        int row = m0 + tm*2 + i;
        float4 o = make_float4(acc[i][0]+bb.x, acc[i][1]+bb.y, acc[i][2]+bb.z, acc[i][3]+bb.w);
        *(float4*)&C[row * N + n0 + tn*4] = o;
        if (n0 >= 256 && n0 < 512) {   // K-column range of the qkv GEMM
            uint2 kk = make_uint2(pack2h(o.x, o.y), pack2h(o.z, o.w));
            ((uint2*)g_K16)[row * 64 + ((n0 - 256) >> 2) + tn] = kk;
        }
    }
}

// ===== main edge kernel: fp16 1-pass, CTA=(b,q,half), 4 kt per CTA =====
__global__ void __launch_bounds__(256, 2) edge_mma_kernel(
    const float* __restrict__ edges, const float* __restrict__ b_ss,
    const float* __restrict__ b_edges, float* __restrict__ out_edges)
{
    extern __shared__ float sm[];
    float* sE   = sm;                          // [4][32][68]
    uint32_t* sQK = (uint32_t*)(sm + 8704);    // [32][132] qk fp16x2
    float* sQ   = sm + 12928;                  // 256
    float* sBsh = sm + 13184;                  // 256
    float* sBsc = sm + 13440;                  // 256
    float* sBed = sm + 13696;                  // 64
    uint32_t* sQh = (uint32_t*)(sm + 13760);   // 128: q fp16x2
    uint32_t* sA2h = (uint32_t*)(sm + 13888);  // [32][132] fp16x2

    const int tid = threadIdx.x;
    const int warp = tid >> 5, lane = tid & 31;
    const int wm = warp >> 2, wn = warp & 3;
    const int g = lane >> 2, t = lane & 3;
    const int b = blockIdx.x >> 9;
    const int q = (blockIdx.x >> 1) & 255;
    const int half = blockIdx.x & 1;
    const int r0 = wm * 16 + g, r1 = r0 + 8;

    const float* ep = edges + (((size_t)(b * 256 + q)) * 256 + half * 128) * 64;
    const int krow = tid >> 3, kseg = (tid & 7) << 2;   // K staging coords

    if (tid < 64) {
        float4 v = *(const float4*)&g_QKV[(b*256+q)*768 + tid*4];
        *(float4*)&sQ[tid*4] = v;
        uint2 qh = make_uint2(pack2h(v.x, v.y), pack2h(v.z, v.w));
        *(uint2*)&sQh[tid*2] = qh;
    }
    else if (tid < 128) *(float4*)&sBsh[(tid-64)*4]  = *(const float4*)&b_ss[(tid-64)*4];
    else if (tid < 192) *(float4*)&sBsc[(tid-128)*4] = *(const float4*)&b_ss[256+(tid-128)*4];
    else if (tid < 208) *(float4*)&sBed[(tid-192)*4] = *(const float4*)&b_edges[(tid-192)*4];

    // stage all 4 edge tiles
    {
        const int er = tid >> 4, ec = (tid & 15) << 2;
#pragma unroll
        for (int i = 0; i < 8; i++) {
            int tile = i >> 1;
            int row = er + (i & 1) * 16;
            float4 v = *(const float4*)(ep + (size_t)(tile*32 + row) * 64 + ec);
            *(float4*)&sE[tile*2176 + row*68 + ec] = v;
        }
    }
    __syncthreads();

    for (int kt4 = 0; kt4 < 4; kt4++) {
        const int kt = half * 4 + kt4;
        const float* sEc = sE + kt4 * 2176;

        // load K fp16 for this kt into registers (coalesced)
        uint4 kreg[4];
#pragma unroll
        for (int j = 0; j < 4; j++)
            kreg[j] = g_K16[((size_t)(b*256 + kt*32 + krow))*32 + kseg + j];

        // ---- GEMM1: shift(acc 0..7) + scale(acc 8..15), fp16 1-pass ----
        float acc[16][4];
#pragma unroll
        for (int i = 0; i < 16; i++) { acc[i][0]=acc[i][1]=acc[i][2]=acc[i][3]=0.f; }
#pragma unroll
        for (int ks = 0; ks < 4; ks++) {
            uint32_t Ah[4];
            {
                int e0 = ks * 16 + 2 * t;
                float2 v00 = *(const float2*)&sEc[r0*68 + e0];
                float2 v10 = *(const float2*)&sEc[r1*68 + e0];
                float2 v01 = *(const float2*)&sEc[r0*68 + e0 + 8];
                float2 v11 = *(const float2*)&sEc[r1*68 + e0 + 8];
                Ah[0] = pack2h(v00.x, v00.y);
                Ah[1] = pack2h(v10.x, v10.y);
                Ah[2] = pack2h(v01.x, v01.y);
                Ah[3] = pack2h(v11.x, v11.y);
            }
#pragma unroll
            for (int tpi = 0; tpi < 4; tpi++) {
                uint4 bh = g_Wss[(ks*32 + 4*wn + tpi)*32 + lane];        // shift
                mma16816h(acc[2*tpi],   Ah, bh.x, bh.y);
                mma16816h(acc[2*tpi+1], Ah, bh.z, bh.w);
                uint4 ch = g_Wss[(ks*32 + 16 + 4*wn + tpi)*32 + lane];   // scale
                mma16816h(acc[8+2*tpi],   Ah, ch.x, ch.y);
                mma16816h(acc[8+2*tpi+1], Ah, ch.z, ch.w);
            }
        }

        // ---- store qk = q*k (fp16) for this kt ----
#pragma unroll
        for (int j = 0; j < 4; j++) {
            uint4 qv = *(uint4*)&sQh[(kseg + j) * 4];   // 8 q halves
            uint2 o0 = make_uint2(hmul2u(kreg[j].x, qv.x), hmul2u(kreg[j].y, qv.y));
            uint2 o1 = make_uint2(hmul2u(kreg[j].z, qv.z), hmul2u(kreg[j].w, qv.w));
            int base = krow*132 + (kseg + j) * 4;
            *(uint2*)&sQK[base]     = o0;
            *(uint2*)&sQK[base + 2] = o1;
        }
        __syncthreads();   // qk staged

        // ---- epilogue: ne, logits, lrelu -> sA2 ----
        float lg00 = 0.f, lg01 = 0.f, lg10 = 0.f, lg11 = 0.f;
#pragma unroll
        for (int lt = 0; lt < 8; lt++) {
            int c0 = wn * 64 + lt * 8 + 2 * t;
            int cw = c0 >> 1;
            uint32_t w0 = sQK[r0*132 + cw], w1 = sQK[r1*132 + cw];
            float2 qk0 = __half22float2(*(__half2*)&w0);
            float2 qk1 = __half22float2(*(__half2*)&w1);
            float2 sc01 = *(const float2*)&sBsc[c0];
            float2 sh01 = *(const float2*)&sBsh[c0];
            float ne00 = fmaf(qk0.x, acc[8+lt][0] + sc01.x, qk0.x) + acc[lt][0] + sh01.x;
            float ne01 = fmaf(qk0.y, acc[8+lt][1] + sc01.y, qk0.y) + acc[lt][1] + sh01.y;
            float ne10 = fmaf(qk1.x, acc[8+lt][2] + sc01.x, qk1.x) + acc[lt][2] + sh01.x;
            float ne11 = fmaf(qk1.y, acc[8+lt][3] + sc01.y, qk1.y) + acc[lt][3] + sh01.y;
            if (lt < 4) { lg00 += ne00 + ne01; lg10 += ne10 + ne11; }
            else        { lg01 += ne00 + ne01; lg11 += ne10 + ne11; }
            float p00 = ne00 > 0.f ? ne00 : 0.1f*ne00;
            float p01 = ne01 > 0.f ? ne01 : 0.1f*ne01;
            float p10 = ne10 > 0.f ? ne10 : 0.1f*ne10;
            float p11 = ne11 > 0.f ? ne11 : 0.1f*ne11;
            int cp = wn * 32 + lt * 4 + t;
            sA2h[r0*132 + cp] = pack2h(p00, p01);
            sA2h[r1*132 + cp] = pack2h(p10, p11);
        }
        lg00 += __shfl_xor_sync(0xffffffffu, lg00, 1); lg00 += __shfl_xor_sync(0xffffffffu, lg00, 2);
        lg01 += __shfl_xor_sync(0xffffffffu, lg01, 1); lg01 += __shfl_xor_sync(0xffffffffu, lg01, 2);
        lg10 += __shfl_xor_sync(0xffffffffu, lg10, 1); lg10 += __shfl_xor_sync(0xffffffffu, lg10, 2);
        lg11 += __shfl_xor_sync(0xffffffffu, lg11, 1); lg11 += __shfl_xor_sync(0xffffffffu, lg11, 2);
        if (t == 0) {
            const float SC = 0.17677669529663687f;
            int kk = kt * 32;
            g_att[(((size_t)(b*8 + 2*wn+0))*256 + kk + r0)*256 + q] = lg00 * SC;
            g_att[(((size_t)(b*8 + 2*wn+1))*256 + kk + r0)*256 + q] = lg01 * SC;
            g_att[(((size_t)(b*8 + 2*wn+0))*256 + kk + r1)*256 + q] = lg10 * SC;
            g_att[(((size_t)(b*8 + 2*wn+1))*256 + kk + r1)*256 + q] = lg11 * SC;
        }
        __syncthreads();

        // ---- GEMM2: out = lrelu(ne)[32,256] @ W_edges[256,64], fp16 1-pass ----
        float c2a[4] = {}, c2b[4] = {};
#pragma unroll
        for (int ks = 0; ks < 16; ks++) {
            uint32_t ah[4];
            ah[0] = sA2h[r0*132 + ks*8 + t];
            ah[1] = sA2h[r1*132 + ks*8 + t];
            ah[2] = sA2h[r0*132 + ks*8 + 4 + t];
            ah[3] = sA2h[r1*132 + ks*8 + 4 + t];
            uint4 bh = g_Wed[(ks*4 + wn)*32 + lane];
            mma16816h(c2a, ah, bh.x, bh.y); mma16816h(c2b, ah, bh.z, bh.w);
        }
        float* op = out_edges + (((size_t)(b*256+q))*256 + kt*32)*64;
        {
            int e0 = wn * 16 + 2 * t;
            *(float2*)&op[r0*64 + e0]     = make_float2(c2a[0] + sBed[e0],   c2a[1] + sBed[e0+1]);
            *(float2*)&op[r1*64 + e0]     = make_float2(c2a[2] + sBed[e0],   c2a[3] + sBed[e0+1]);
            *(float2*)&op[r0*64 + e0 + 8] = make_float2(c2b[0] + sBed[e0+8], c2b[1] + sBed[e0+9]);
            *(float2*)&op[r1*64 + e0 + 8] = make_float2(c2b[2] + sBed[e0+8], c2b[3] + sBed[e0+9]);
        }
        __syncthreads();
    }
}

// ===== softmax over q for each (b,h,k) =====
__global__ void __launch_bounds__(256) softmax_q_kernel(float* __restrict__ lg)
{
    const int row = blockIdx.x * 8 + (threadIdx.x >> 5);
    const int lane = threadIdx.x & 31;
    float* p = lg + (size_t)row * 256;
    float4 v0 = *(float4*)&p[lane * 8];
    float4 v1 = *(float4*)&p[lane * 8 + 4];
    float v[8] = { v0.x, v0.y, v0.z, v0.w, v1.x, v1.y, v1.z, v1.w };
    float m = v[0];
#pragma unroll
    for (int i = 1; i < 8; i++) m = fmaxf(m, v[i]);
#pragma unroll
    for (int o = 16; o > 0; o >>= 1) m = fmaxf(m, __shfl_xor_sync(0xffffffffu, m, o));
    float s = 0.f;
#pragma unroll
    for (int i = 0; i < 8; i++) { v[i] = __expf(v[i] - m); s += v[i]; }
#pragma unroll
    for (int o = 16; o > 0; o >>= 1) s += __shfl_xor_sync(0xffffffffu, s, o);
    float inv = 1.f / s;
    *(float4*)&p[lane * 8]     = make_float4(v[0]*inv, v[1]*inv, v[2]*inv, v[3]*inv);
    *(float4*)&p[lane * 8 + 4] = make_float4(v[4]*inv, v[5]*inv, v[6]*inv, v[7]*inv);
}

// ===== attn @ V, k-split, atomics into zeroed g_wt =====
__global__ void __launch_bounds__(256) attnv2_kernel(const float* __restrict__ att)
{
    __shared__ float sv[32][32];
    const int b = blockIdx.z >> 3, h = blockIdx.z & 7;
    const int kc = blockIdx.y, qc = blockIdx.x;
    const int dg = threadIdx.x >> 6, qq = threadIdx.x & 63;
    const int q = qc * 64 + qq;
    {
        int row = threadIdx.x >> 3, c4 = (threadIdx.x & 7) << 2;
        *(float4*)&sv[row][c4] =
            *(const float4*)&g_QKV[((b << 8) + kc * 32 + row) * 768 + 512 + h * 32 + c4];
    }
    __syncthreads();
    const float* ap = att + (((size_t)((b << 3) + h)) * 256 + kc * 32) * 256 + q;
    float acc[8] = {};
#pragma unroll
    for (int kk = 0; kk < 32; kk++) {
        float a = ap[(size_t)kk * 256];
        float4 u0 = *(float4*)&sv[kk][dg * 8];
        float4 u1 = *(float4*)&sv[kk][dg * 8 + 4];
        acc[0]+=a*u0.x; acc[1]+=a*u0.y; acc[2]+=a*u0.z; acc[3]+=a*u0.w;
        acc[4]+=a*u1.x; acc[5]+=a*u1.y; acc[6]+=a*u1.z; acc[7]+=a*u1.w;
    }
    float* wp = &g_wt[((b << 8) + q) * 256 + h * 32 + dg * 8];
#pragma unroll
    for (int j = 0; j < 8; j++) atomicAdd(wp + j, acc[j]);
}

// ===== launch =====
extern "C" void kernel_launch(void* const* d_in, const int* in_sizes, int n_in,
                              void* d_out, int out_size)
{
    const float* nodes   = (const float*)d_in[0];
    const float* edges   = (const float*)d_in[1];
    const float* W_qkv   = (const float*)d_in[2];
    const float* b_qkv   = (const float*)d_in[3];
    const float* W_ss    = (const float*)d_in[4];
    const float* b_ss    = (const float*)d_in[5];
    const float* W_nodes = (const float*)d_in[6];
    const float* b_nodes = (const float*)d_in[7];
    const float* W_edges = (const float*)d_in[8];
    const float* b_edges = (const float*)d_in[9];

    float* out_nodes = (float*)d_out;
    float* out_edges = out_nodes + 512 * 256;

    float *qkvp = nullptr, *attp = nullptr, *wtp = nullptr;
    cudaGetSymbolAddress((void**)&qkvp, g_QKV);
    cudaGetSymbolAddress((void**)&attp, g_att);
    cudaGetSymbolAddress((void**)&wtp, g_wt);

    // sE(8704) + sQK(4224) + sQ/biases/qh(960) + sA2(4224) = 18112 floats
    const int EDGE_SMEM = 18112 * sizeof(float);   // 72448 B
    cudaFuncSetAttribute(edge_mma_kernel,
                         cudaFuncAttributeMaxDynamicSharedMemorySize, EDGE_SMEM);

    // edge_mma is the 4th launch -> ncu captures it
    prep_wss_kernel<<<16, 256>>>(W_ss);
    prep_wed_kernel<<<8, 256>>>(W_edges);
    gemm_bias_kernel<<<(512/32)*(768/64), 256>>>(nodes, W_qkv, b_qkv, qkvp, 512, 256, 768);
    edge_mma_kernel<<<1024, 256, EDGE_SMEM>>>(edges, b_ss, b_edges, out_edges);
    zero_wt_kernel<<<128, 256>>>();
    softmax_q_kernel<<<512, 256>>>(attp);
    attnv2_kernel<<<dim3(4, 8, 16), 256>>>(attp);
    gemm_bias_kernel<<<(512/32)*(256/64), 256>>>(wtp, W_nodes, b_nodes, out_nodes, 512, 256, 256);
}

// round 14
// speedup vs baseline: 1.2657x; 1.2657x over previous
#include <cuda_runtime.h>
#include <cuda_fp16.h>
#include <cstdint>

// ---------------------------------------------------------------------------
// R14: edge = exact R12 (best, 86us). qkv + node projections moved to fp16
// mma.sync GEMM (gemm_mma_kernel) with frag-linear weight images.
// ---------------------------------------------------------------------------

__device__ __forceinline__ void mma16816h(float c[4], const uint32_t a[4],
                                          uint32_t b0, uint32_t b1) {
    asm volatile("mma.sync.aligned.m16n8k16.row.col.f32.f16.f16.f32 "
        "{%0,%1,%2,%3},{%4,%5,%6,%7},{%8,%9},{%0,%1,%2,%3};"
        : "+f"(c[0]), "+f"(c[1]), "+f"(c[2]), "+f"(c[3])
        : "r"(a[0]), "r"(a[1]), "r"(a[2]), "r"(a[3]), "r"(b0), "r"(b1));
}
__device__ __forceinline__ uint32_t pack2h(float v0, float v1) {
    __half2 hh = __floats2half2_rn(v0, v1);
    return *(uint32_t*)&hh;
}

// ===== scratch =====
__device__ float g_QKV[512 * 768];          // [b*256+n][768] q|k|v
__device__ float g_att[2 * 8 * 256 * 256];  // [b][h][k][q]
__device__ float g_wt[512 * 256];
__device__ uint4 g_Wss[4096];    // [ks4][tp32][lane32]
__device__ uint4 g_Wed[2048];    // [ks16][tp4][lane32]
__device__ uint4 g_Wqkv[24576];  // [ks16][tp48][lane32]
__device__ uint4 g_Wnd[8192];    // [ks16][tp16][lane32]

__global__ void __launch_bounds__(256) zero_wt_kernel()
{
    int i = blockIdx.x * 256 + threadIdx.x;
    ((float4*)g_wt)[i] = make_float4(0.f, 0.f, 0.f, 0.f);
}

// generic frag-image fill: W[K=256 rows][N cols] -> img[(ks*NTP+tp)*32+lane]
__device__ __forceinline__ void fill_img(const float* __restrict__ W, uint4* img,
                                         int idx, int N, int NTP) {
    int lane = idx & 31, tp = (idx >> 5) % NTP, ks = idx / (NTP * 32);
    int gq = lane >> 2, tq = lane & 3;
    uint32_t r4[4];
#pragma unroll
    for (int r = 0; r < 4; r++) {
        int tile = 2 * tp + (r >> 1);
        int bsel = r & 1;
        int n = tile * 8 + gq;
        int e0 = ks * 16 + 2 * tq + 8 * bsel;
        r4[r] = pack2h(W[e0 * N + n], W[(e0 + 1) * N + n]);
    }
    img[idx] = make_uint4(r4[0], r4[1], r4[2], r4[3]);
}

// ===== prep: W_ss (16 blocks) + W_edges (8 blocks) =====
__global__ void __launch_bounds__(256) prep_small_kernel(
    const float* __restrict__ W_ss, const float* __restrict__ W_edges)
{
    int bidx = blockIdx.x;
    if (bidx < 16) {   // W_ss: 4096 uint4, K=64: ks4, NTP=32
        int idx = bidx * 256 + threadIdx.x;
        int lane = idx & 31, tp = (idx >> 5) & 31, ks = idx >> 10;
        int gq = lane >> 2, tq = lane & 3;
        uint32_t r4[4];
#pragma unroll
        for (int r = 0; r < 4; r++) {
            int tile = 2 * tp + (r >> 1);
            int bsel = r & 1;
            int n = tile * 8 + gq;
            int e0 = ks * 16 + 2 * tq + 8 * bsel;
            r4[r] = pack2h(W_ss[e0 * 512 + n], W_ss[(e0 + 1) * 512 + n]);
        }
        g_Wss[idx] = make_uint4(r4[0], r4[1], r4[2], r4[3]);
    } else {           // W_edges: 2048 uint4, K=256: ks16, NTP=4
        int idx = (bidx - 16) * 256 + threadIdx.x;
        fill_img(W_edges, g_Wed, idx, 64, 4);
    }
}
// ===== prep: W_qkv (96 blocks) + W_nodes (32 blocks) =====
__global__ void __launch_bounds__(256) prep_big_kernel(
    const float* __restrict__ W_qkv, const float* __restrict__ W_nodes)
{
    int bidx = blockIdx.x;
    if (bidx < 96) fill_img(W_qkv, g_Wqkv, bidx * 256 + threadIdx.x, 768, 48);
    else           fill_img(W_nodes, g_Wnd, (bidx - 96) * 256 + threadIdx.x, 256, 16);
}

// ===== mma GEMM with bias: C[M,N] = A[M,256] @ W + bias (fp16 1-pass) =====
// CTA: 32 M-rows x 64 N-cols; 8 warps = wm2 x wn4 (warp: M16 x N16).
__global__ void __launch_bounds__(256) gemm_mma_kernel(
    const float* __restrict__ A, const uint4* __restrict__ img,
    const float* __restrict__ bias, float* __restrict__ C, int N)
{
    __shared__ uint32_t sA16[32 * 132];
    __shared__ float sBias[64];
    const int K = 256;
    const int nb = N >> 6;
    const int m0 = (blockIdx.x / nb) << 5, n0 = (blockIdx.x % nb) << 6;
    const int tid = threadIdx.x;
    const int warp = tid >> 5, lane = tid & 31;
    const int wm = warp >> 2, wn = warp & 3;
    const int g = lane >> 2, t = lane & 3;
    const int NTP = N >> 4;

    // stage A 32 x 256 fp32 -> fp16 smem (rows stride 132 words)
#pragma unroll
    for (int i = 0; i < 8; i++) {
        int idx4 = tid + i * 256;              // 2048 float4
        int row = idx4 >> 6, c4 = idx4 & 63;
        float4 v = *(const float4*)&A[(m0 + row) * K + c4 * 4];
        uint2 p = make_uint2(pack2h(v.x, v.y), pack2h(v.z, v.w));
        *(uint2*)&sA16[row * 132 + c4 * 2] = p;
    }
    if (tid < 64) sBias[tid] = bias[n0 + tid];
    __syncthreads();

    const int r0 = wm * 16 + g, r1 = r0 + 8;
    float acc0[4] = {}, acc1[4] = {};
#pragma unroll
    for (int ks = 0; ks < 16; ks++) {
        uint32_t a[4];
        a[0] = sA16[r0 * 132 + ks * 8 + t];
        a[1] = sA16[r1 * 132 + ks * 8 + t];
        a[2] = sA16[r0 * 132 + ks * 8 + 4 + t];
        a[3] = sA16[r1 * 132 + ks * 8 + 4 + t];
        uint4 bh = img[((ks * NTP) + (n0 >> 4) + wn) * 32 + lane];
        mma16816h(acc0, a, bh.x, bh.y);
        mma16816h(acc1, a, bh.z, bh.w);
    }
    const int cl = wn * 16 + 2 * t;
    const int c0 = n0 + cl;
    *(float2*)&C[(m0 + r0) * N + c0]     = make_float2(acc0[0] + sBias[cl],   acc0[1] + sBias[cl+1]);
    *(float2*)&C[(m0 + r1) * N + c0]     = make_float2(acc0[2] + sBias[cl],   acc0[3] + sBias[cl+1]);
    *(float2*)&C[(m0 + r0) * N + c0 + 8] = make_float2(acc1[0] + sBias[cl+8], acc1[1] + sBias[cl+9]);
    *(float2*)&C[(m0 + r1) * N + c0 + 8] = make_float2(acc1[2] + sBias[cl+8], acc1[3] + sBias[cl+9]);
}

// ===== main edge kernel (exact R12): fp16 1-pass, CTA=(b,q,half), 4 kt =====
__global__ void __launch_bounds__(256, 2) edge_mma_kernel(
    const float* __restrict__ edges, const float* __restrict__ b_ss,
    const float* __restrict__ b_edges, float* __restrict__ out_edges)
{
    extern __shared__ float sm[];
    float* sE   = sm;                    // [4][32][68]
    float* sQ   = sm + 8704;             // 256
    float* sBsh = sQ + 256;              // 256
    float* sBsc = sBsh + 256;            // 256
    float* sBed = sBsc + 256;            // 64
    uint32_t* sA2h = (uint32_t*)(sBed + 64);  // [32][132] fp16x2

    const int tid = threadIdx.x;
    const int warp = tid >> 5, lane = tid & 31;
    const int wm = warp >> 2, wn = warp & 3;
    const int g = lane >> 2, t = lane & 3;
    const int b = blockIdx.x >> 9;
    const int q = (blockIdx.x >> 1) & 255;
    const int half = blockIdx.x & 1;
    const int r0 = wm * 16 + g, r1 = r0 + 8;

    const float* ep = edges + (((size_t)(b * 256 + q)) * 256 + half * 128) * 64;

    if (tid < 64)       *(float4*)&sQ[tid*4]   = *(const float4*)&g_QKV[(b*256+q)*768 + tid*4];
    else if (tid < 128) *(float4*)&sBsh[(tid-64)*4]  = *(const float4*)&b_ss[(tid-64)*4];
    else if (tid < 192) *(float4*)&sBsc[(tid-128)*4] = *(const float4*)&b_ss[256+(tid-128)*4];
    else if (tid < 208) *(float4*)&sBed[(tid-192)*4] = *(const float4*)&b_edges[(tid-192)*4];

    {
        const int er = tid >> 4, ec = (tid & 15) << 2;
#pragma unroll
        for (int i = 0; i < 8; i++) {
            int tile = i >> 1;
            int row = er + (i & 1) * 16;
            float4 v = *(const float4*)(ep + (size_t)(tile*32 + row) * 64 + ec);
            *(float4*)&sE[tile*2176 + row*68 + ec] = v;
        }
    }
    __syncthreads();

    for (int kt4 = 0; kt4 < 4; kt4++) {
        const int kt = half * 4 + kt4;
        const float* sEc = sE + kt4 * 2176;

        float acc[16][4];
#pragma unroll
        for (int i = 0; i < 16; i++) { acc[i][0]=acc[i][1]=acc[i][2]=acc[i][3]=0.f; }
#pragma unroll
        for (int ks = 0; ks < 4; ks++) {
            uint32_t Ah[4];
            {
                int e0 = ks * 16 + 2 * t;
                float2 v00 = *(const float2*)&sEc[r0*68 + e0];
                float2 v10 = *(const float2*)&sEc[r1*68 + e0];
                float2 v01 = *(const float2*)&sEc[r0*68 + e0 + 8];
                float2 v11 = *(const float2*)&sEc[r1*68 + e0 + 8];
                Ah[0] = pack2h(v00.x, v00.y);
                Ah[1] = pack2h(v10.x, v10.y);
                Ah[2] = pack2h(v01.x, v01.y);
                Ah[3] = pack2h(v11.x, v11.y);
            }
#pragma unroll
            for (int tpi = 0; tpi < 4; tpi++) {
                uint4 bh = g_Wss[(ks*32 + 4*wn + tpi)*32 + lane];
                mma16816h(acc[2*tpi],   Ah, bh.x, bh.y);
                mma16816h(acc[2*tpi+1], Ah, bh.z, bh.w);
                uint4 ch = g_Wss[(ks*32 + 16 + 4*wn + tpi)*32 + lane];
                mma16816h(acc[8+2*tpi],   Ah, ch.x, ch.y);
                mma16816h(acc[8+2*tpi+1], Ah, ch.z, ch.w);
            }
        }

        const float* kr0 = &g_QKV[(b*256 + kt*32 + r0)*768 + 256];
        const float* kr1 = &g_QKV[(b*256 + kt*32 + r1)*768 + 256];
        float lg00 = 0.f, lg01 = 0.f, lg10 = 0.f, lg11 = 0.f;
#pragma unroll
        for (int lt = 0; lt < 8; lt++) {
            int c0 = wn * 64 + lt * 8 + 2 * t;
            float2 k0v = *(const float2*)(kr0 + c0);
            float2 k1v = *(const float2*)(kr1 + c0);
            float q0 = sQ[c0], q1 = sQ[c0+1];
            float qk00 = q0 * k0v.x, qk01 = q1 * k0v.y;
            float qk10 = q0 * k1v.x, qk11 = q1 * k1v.y;
            float ne00 = fmaf(qk00, acc[8+lt][0] + sBsc[c0],   qk00) + acc[lt][0] + sBsh[c0];
            float ne01 = fmaf(qk01, acc[8+lt][1] + sBsc[c0+1], qk01) + acc[lt][1] + sBsh[c0+1];
            float ne10 = fmaf(qk10, acc[8+lt][2] + sBsc[c0],   qk10) + acc[lt][2] + sBsh[c0];
            float ne11 = fmaf(qk11, acc[8+lt][3] + sBsc[c0+1], qk11) + acc[lt][3] + sBsh[c0+1];
            if (lt < 4) { lg00 += ne00 + ne01; lg10 += ne10 + ne11; }
            else        { lg01 += ne00 + ne01; lg11 += ne10 + ne11; }
            float p00 = ne00 > 0.f ? ne00 : 0.1f*ne00;
            float p01 = ne01 > 0.f ? ne01 : 0.1f*ne01;
            float p10 = ne10 > 0.f ? ne10 : 0.1f*ne10;
            float p11 = ne11 > 0.f ? ne11 : 0.1f*ne11;
            int cp = wn * 32 + lt * 4 + t;
            sA2h[r0*132 + cp] = pack2h(p00, p01);
            sA2h[r1*132 + cp] = pack2h(p10, p11);
        }
        lg00 += __shfl_xor_sync(0xffffffffu, lg00, 1); lg00 += __shfl_xor_sync(0xffffffffu, lg00, 2);
        lg01 += __shfl_xor_sync(0xffffffffu, lg01, 1); lg01 += __shfl_xor_sync(0xffffffffu, lg01, 2);
        lg10 += __shfl_xor_sync(0xffffffffu, lg10, 1); lg10 += __shfl_xor_sync(0xffffffffu, lg10, 2);
        lg11 += __shfl_xor_sync(0xffffffffu, lg11, 1); lg11 += __shfl_xor_sync(0xffffffffu, lg11, 2);
        if (t == 0) {
            const float SC = 0.17677669529663687f;
            int kk = kt * 32;
            g_att[(((size_t)(b*8 + 2*wn+0))*256 + kk + r0)*256 + q] = lg00 * SC;
            g_att[(((size_t)(b*8 + 2*wn+1))*256 + kk + r0)*256 + q] = lg01 * SC;
            g_att[(((size_t)(b*8 + 2*wn+0))*256 + kk + r1)*256 + q] = lg10 * SC;
            g_att[(((size_t)(b*8 + 2*wn+1))*256 + kk + r1)*256 + q] = lg11 * SC;
        }
        __syncthreads();

        float c2a[4] = {}, c2b[4] = {};
#pragma unroll
        for (int ks = 0; ks < 16; ks++) {
            uint32_t ah[4];
            ah[0] = sA2h[r0*132 + ks*8 + t];
            ah[1] = sA2h[r1*132 + ks*8 + t];
            ah[2] = sA2h[r0*132 + ks*8 + 4 + t];
            ah[3] = sA2h[r1*132 + ks*8 + 4 + t];
            uint4 bh = g_Wed[(ks*4 + wn)*32 + lane];
            mma16816h(c2a, ah, bh.x, bh.y); mma16816h(c2b, ah, bh.z, bh.w);
        }
        float* op = out_edges + (((size_t)(b*256+q))*256 + kt*32)*64;
        {
            int e0 = wn * 16 + 2 * t;
            *(float2*)&op[r0*64 + e0]     = make_float2(c2a[0] + sBed[e0],   c2a[1] + sBed[e0+1]);
            *(float2*)&op[r1*64 + e0]     = make_float2(c2a[2] + sBed[e0],   c2a[3] + sBed[e0+1]);
            *(float2*)&op[r0*64 + e0 + 8] = make_float2(c2b[0] + sBed[e0+8], c2b[1] + sBed[e0+9]);
            *(float2*)&op[r1*64 + e0 + 8] = make_float2(c2b[2] + sBed[e0+8], c2b[3] + sBed[e0+9]);
        }
        __syncthreads();
    }
}

// ===== softmax over q for each (b,h,k) =====
__global__ void __launch_bounds__(256) softmax_q_kernel(float* __restrict__ lg)
{
    const int row = blockIdx.x * 8 + (threadIdx.x >> 5);
    const int lane = threadIdx.x & 31;
    float* p = lg + (size_t)row * 256;
    float4 v0 = *(float4*)&p[lane * 8];
    float4 v1 = *(float4*)&p[lane * 8 + 4];
    float v[8] = { v0.x, v0.y, v0.z, v0.w, v1.x, v1.y, v1.z, v1.w };
    float m = v[0];
#pragma unroll
    for (int i = 1; i < 8; i++) m = fmaxf(m, v[i]);
#pragma unroll
    for (int o = 16; o > 0; o >>= 1) m = fmaxf(m, __shfl_xor_sync(0xffffffffu, m, o));
    float s = 0.f;
#pragma unroll
    for (int i = 0; i < 8; i++) { v[i] = __expf(v[i] - m); s += v[i]; }
#pragma unroll
    for (int o = 16; o > 0; o >>= 1) s += __shfl_xor_sync(0xffffffffu, s, o);
    float inv = 1.f / s;
    *(float4*)&p[lane * 8]     = make_float4(v[0]*inv, v[1]*inv, v[2]*inv, v[3]*inv);
    *(float4*)&p[lane * 8 + 4] = make_float4(v[4]*inv, v[5]*inv, v[6]*inv, v[7]*inv);
}

// ===== attn @ V, k-split, atomics into zeroed g_wt =====
__global__ void __launch_bounds__(256) attnv2_kernel(const float* __restrict__ att)
{
    __shared__ float sv[32][32];
    const int b = blockIdx.z >> 3, h = blockIdx.z & 7;
    const int kc = blockIdx.y, qc = blockIdx.x;
    const int dg = threadIdx.x >> 6, qq = threadIdx.x & 63;
    const int q = qc * 64 + qq;
    {
        int row = threadIdx.x >> 3, c4 = (threadIdx.x & 7) << 2;
        *(float4*)&sv[row][c4] =
            *(const float4*)&g_QKV[((b << 8) + kc * 32 + row) * 768 + 512 + h * 32 + c4];
    }
    __syncthreads();
    const float* ap = att + (((size_t)((b << 3) + h)) * 256 + kc * 32) * 256 + q;
    float acc[8] = {};
#pragma unroll
    for (int kk = 0; kk < 32; kk++) {
        float a = ap[(size_t)kk * 256];
        float4 u0 = *(float4*)&sv[kk][dg * 8];
        float4 u1 = *(float4*)&sv[kk][dg * 8 + 4];
        acc[0]+=a*u0.x; acc[1]+=a*u0.y; acc[2]+=a*u0.z; acc[3]+=a*u0.w;
        acc[4]+=a*u1.x; acc[5]+=a*u1.y; acc[6]+=a*u1.z; acc[7]+=a*u1.w;
    }
    float* wp = &g_wt[((b << 8) + q) * 256 + h * 32 + dg * 8];
#pragma unroll
    for (int j = 0; j < 8; j++) atomicAdd(wp + j, acc[j]);
}

// ===== launch =====
extern "C" void kernel_launch(void* const* d_in, const int* in_sizes, int n_in,
                              void* d_out, int out_size)
{
    const float* nodes   = (const float*)d_in[0];
    const float* edges   = (const float*)d_in[1];
    const float* W_qkv   = (const float*)d_in[2];
    const float* b_qkv   = (const float*)d_in[3];
    const float* W_ss    = (const float*)d_in[4];
    const float* b_ss    = (const float*)d_in[5];
    const float* W_nodes = (const float*)d_in[6];
    const float* b_nodes = (const float*)d_in[7];
    const float* W_edges = (const float*)d_in[8];
    const float* b_edges = (const float*)d_in[9];

    float* out_nodes = (float*)d_out;
    float* out_edges = out_nodes + 512 * 256;

    float *qkvp = nullptr, *attp = nullptr, *wtp = nullptr;
    cudaGetSymbolAddress((void**)&qkvp, g_QKV);
    cudaGetSymbolAddress((void**)&attp, g_att);
    cudaGetSymbolAddress((void**)&wtp, g_wt);
    uint4* wqkvp = nullptr; cudaGetSymbolAddress((void**)&wqkvp, g_Wqkv);
    uint4* wndp  = nullptr; cudaGetSymbolAddress((void**)&wndp, g_Wnd);

    const int EDGE_SMEM = (8704 + 832 + 4224) * sizeof(float);   // 55040 B
    cudaFuncSetAttribute(edge_mma_kernel,
                         cudaFuncAttributeMaxDynamicSharedMemorySize, EDGE_SMEM);

    // edge_mma stays the 4th launch (ncu capture point)
    prep_big_kernel<<<128, 256>>>(W_qkv, W_nodes);
    prep_small_kernel<<<24, 256>>>(W_ss, W_edges);
    gemm_mma_kernel<<<(512/32)*(768/64), 256>>>(nodes, wqkvp, b_qkv, qkvp, 768);
    edge_mma_kernel<<<1024, 256, EDGE_SMEM>>>(edges, b_ss, b_edges, out_edges);
    zero_wt_kernel<<<128, 256>>>();
    softmax_q_kernel<<<512, 256>>>(attp);
    attnv2_kernel<<<dim3(4, 8, 16), 256>>>(attp);
    gemm_mma_kernel<<<(512/32)*(256/64), 256>>>(wtp, wndp, b_nodes, out_nodes, 256);
}